// round 3
// baseline (speedup 1.0000x reference)
#include <cuda_runtime.h>
#include <math.h>

// Shapelet_66932770341112 on sm_103a
// B=16, C=8, T=512, L=24, STRIDE=2, N=64, M=245, EPS=1
// d(b,m,n,c) = (1/L) * sum_l |x[b,c,2m+l] - w[n,c,l]| * pcm[c,m]
// out[0 : B*N*C]       = exp(-min_m d^2)
// out[B*N*C : 2*B*N*C] = min_m d

#define BB 16
#define CC 8
#define TT 512
#define LL 24
#define NN 64
#define MM 245
#define LP (LL/2)          // 12 float2 pairs
#define NHALF 32           // n per thread-half
#define CHUNK 16           // n per reduction chunk

typedef unsigned long long ull;

__device__ __forceinline__ ull add_f32x2(ull a, ull b) {
    ull r;
    asm("add.rn.f32x2 %0, %1, %2;" : "=l"(r) : "l"(a), "l"(b));
    return r;
}
__device__ __forceinline__ ull pack2(float lo, float hi) {
    ull r;
    asm("mov.b64 %0, {%1, %2};" : "=l"(r) : "f"(lo), "f"(hi));
    return r;
}
__device__ __forceinline__ float lo32(ull v) { return __int_as_float((unsigned)(v & 0xffffffffULL)); }
__device__ __forceinline__ float hi32(ull v) { return __int_as_float((unsigned)(v >> 32)); }

__global__ __launch_bounds__(512, 1)
void shapelet_kernel(const float* __restrict__ x,
                     const float* __restrict__ w,
                     const float* __restrict__ pcm,
                     float* __restrict__ out)
{
    __shared__ ull    xsm[256 + LP];          // x row as (even,odd) pairs + zero pad
    __shared__ float4 wneg4[NN][LP / 2];      // negated weights, 6 float4 per n (6KB)
    __shared__ float  dsm[2][CHUNK][256];     // staged d(m) per n (32KB)

    const int bc   = blockIdx.x;              // b*C + c
    const int b    = bc >> 3;
    const int c    = bc & 7;
    const int tid  = threadIdx.x;
    const int half = tid >> 8;                // 0: n in [0,32), 1: n in [32,64)
    const int m    = tid & 255;
    const int lane = tid & 31;
    const int warp = tid >> 5;                // 0..15

    // ---- load x row once per bc (256 float2), zero-pad tail ----
    if (tid < 256) {
        ((float2*)xsm)[tid] = ((const float2*)(x + bc * TT))[tid];
    } else if (tid < 256 + LP) {
        ((float2*)xsm)[tid] = make_float2(0.f, 0.f);
    }
    // ---- load all 64 shapelets' weights for channel c, negated (1536 floats) ----
    for (int i = tid; i < NN * LL; i += 512) {
        const int n = i / LL;
        const int l = i % LL;
        ((float*)wneg4)[n * LL + l] = -w[(n * CC + c) * LL + l];
    }
    __syncthreads();

    // ---- per-thread x window in registers (24 regs) ----
    ull xw[LP];
#pragma unroll
    for (int k = 0; k < LP; ++k) xw[k] = xsm[m + k];

    const float INF = __int_as_float(0x7f800000);
    const float pen   = (m < MM) ? pcm[c * MM + m] * (1.0f / (float)LL) : 0.0f;
    const float guard = (m < MM) ? 0.0f : INF;   // forces d=INF for padding m

    const ull ABS2 = 0x7fffffff7fffffffULL;
    const int nbase = half * NHALF;

    for (int q = 0; q < NHALF / CHUNK; ++q) {
#pragma unroll 4
        for (int j = 0; j < CHUNK; ++j) {
            const int n = nbase + q * CHUNK + j;
            const float4* wp = wneg4[n];
            ull a0 = 0ULL, a1 = 0ULL;
#pragma unroll
            for (int k = 0; k < LP / 2; ++k) {
                const float4 wv = wp[k];
                const ull wlo = pack2(wv.x, wv.y);
                const ull whi = pack2(wv.z, wv.w);
                a0 = add_f32x2(a0, add_f32x2(xw[2 * k],     wlo) & ABS2);
                a1 = add_f32x2(a1, add_f32x2(xw[2 * k + 1], whi) & ABS2);
            }
            a0 = add_f32x2(a0, a1);
            const float s = lo32(a0) + hi32(a0);
            dsm[half][j][m] = fmaf(s, pen, guard);
        }
        __syncthreads();

        // ---- 16 warps reduce 32 staged rows: warp w handles rows (w&7), (w&7)+8
        //      of half (w>>3); each row is min over 256 m values ----
        const int h = warp >> 3;
#pragma unroll
        for (int rr = 0; rr < 2; ++rr) {
            const int r = (warp & 7) + rr * 8;
            const float* row = dsm[h][r];
            float mn = INF, mn2 = INF;
#pragma unroll
            for (int i = 0; i < 8; ++i) {
                const float v = row[lane + i * 32];
                mn  = fminf(mn, v);
                mn2 = fminf(mn2, v * v);
            }
#pragma unroll
            for (int off = 16; off; off >>= 1) {
                mn  = fminf(mn,  __shfl_xor_sync(0xffffffffu, mn,  off));
                mn2 = fminf(mn2, __shfl_xor_sync(0xffffffffu, mn2, off));
            }
            if (lane == 0) {
                const int n = h * NHALF + q * CHUNK + r;
                const int o = (b * NN + n) * CC + c;
                out[o] = expf(-mn2);
                out[BB * NN * CC + o] = mn;
            }
        }
        __syncthreads();   // dsm reused next chunk
    }
}

extern "C" void kernel_launch(void* const* d_in, const int* in_sizes, int n_in,
                              void* d_out, int out_size)
{
    const float* x   = (const float*)d_in[0];   // (B, C, T)
    const float* w   = (const float*)d_in[1];   // (N, C, L)
    const float* pcm = (const float*)d_in[2];   // (C, M)
    float* out = (float*)d_out;

    shapelet_kernel<<<BB * CC, 512>>>(x, w, pcm, out);   // 128 blocks, 1 wave
}

// round 6
// speedup vs baseline: 1.2149x; 1.2149x over previous
#include <cuda_runtime.h>
#include <math.h>

// Shapelet_66932770341112 on sm_103a
// B=16, C=8, T=512, L=24, STRIDE=2, N=64, M=245, EPS=1
// d(b,m,n,c) = (1/L) * sum_l |x[b,c,2m+l] - w[n,c,l]| * pcm[c,m]
// out[0 : B*N*C]       = exp(-min_m d^2)
// out[B*N*C : 2*B*N*C] = min_m d

#define BB 16
#define CC 8
#define TT 512
#define LL 24
#define NN 64
#define MM 245
#define G  8               // n per thread-half
#define NBLK (2*G)         // n per block = 16

typedef unsigned long long ull;

__device__ __forceinline__ ull add_f32x2(ull a, ull b) {
    ull r;
    asm("add.rn.f32x2 %0, %1, %2;" : "=l"(r) : "l"(a), "l"(b));
    return r;
}
__device__ __forceinline__ float lo32(ull v) { return __int_as_float((unsigned)(v & 0xffffffffULL)); }
__device__ __forceinline__ float hi32(ull v) { return __int_as_float((unsigned)(v >> 32)); }

__global__ __launch_bounds__(256, 4)
void shapelet_kernel(const float* __restrict__ x,
                     const float* __restrict__ w,
                     const float* __restrict__ pcm,
                     float* __restrict__ out)
{
    // x row as (even,odd) float2 pairs: pair(t) = (x[2t], x[2t+1]).
    // For position m, weight pair j corresponds to x pair (m + j).
    __shared__ ull    xsm[272];            // 256 pairs + zero pad
    __shared__ ull    wneg[NBLK][12];      // 16 shapelets, negated, as pairs
    __shared__ float2 dsm[NBLK][128];      // per-(n, m-pair) (dmin, d2min)

    const int bc    = blockIdx.x;          // b*C + c
    const int b     = bc >> 3;
    const int c     = bc & 7;
    const int n0    = blockIdx.y * NBLK;   // first shapelet of this block
    const int tid   = threadIdx.x;
    const int mpair = tid & 127;           // handles m0 = 2*mpair, m1 = m0+1
    const int half  = tid >> 7;            // n subset: [n0+half*G, +G)
    const int lane  = tid & 31;
    const int warp  = tid >> 5;            // 0..7

    // ---- x row: 256 float2 pairs + zero pad ----
    ((float2*)xsm)[tid] = ((const float2*)(x + bc * TT))[tid];
    if (tid < 16) ((float2*)xsm)[256 + tid] = make_float2(0.f, 0.f);

    // ---- 16 shapelets' weights for channel c, negated (384 floats, strided) ----
    for (int i = tid; i < NBLK * LL; i += 256) {
        const int j = i / LL;
        const int l = i % LL;
        ((float*)wneg)[j * LL + l] = -w[((n0 + j) * CC + c) * LL + l];
    }
    __syncthreads();

    // ---- register window covering m0 and m0+1: xw[k] = pair(m0 + k) ----
    const int m0 = 2 * mpair;
    ull xw[13];
#pragma unroll
    for (int k = 0; k < 13; ++k) xw[k] = xsm[m0 + k];    // FIX: base m0, not mpair

    const float INF = __int_as_float(0x7f800000);
    const float pen0   = (m0     < MM) ? pcm[c * MM + m0]     * (1.0f / (float)LL) : 0.0f;
    const float pen1   = (m0 + 1 < MM) ? pcm[c * MM + m0 + 1] * (1.0f / (float)LL) : 0.0f;
    const float guard0 = (m0     < MM) ? 0.0f : INF;
    const float guard1 = (m0 + 1 < MM) ? 0.0f : INF;

    const ull ABS2 = 0x7fffffff7fffffffULL;

#pragma unroll
    for (int j = 0; j < G; ++j) {
        const int r = half * G + j;                       // local n index
        const ulonglong2* wp = (const ulonglong2*)wneg[r];
        ull a0 = 0ULL, a1 = 0ULL, b0 = 0ULL, b1 = 0ULL;   // 4 independent chains
#pragma unroll
        for (int k = 0; k < 6; ++k) {
            const ulonglong2 wv = wp[k];                  // weight pairs 2k, 2k+1
            a0 = add_f32x2(a0, add_f32x2(xw[2 * k],     wv.x) & ABS2);  // m0,  wpair 2k
            b0 = add_f32x2(b0, add_f32x2(xw[2 * k + 1], wv.x) & ABS2);  // m0+1,wpair 2k
            a1 = add_f32x2(a1, add_f32x2(xw[2 * k + 1], wv.y) & ABS2);  // m0,  wpair 2k+1
            b1 = add_f32x2(b1, add_f32x2(xw[2 * k + 2], wv.y) & ABS2);  // m0+1,wpair 2k+1
        }
        a0 = add_f32x2(a0, a1);
        b0 = add_f32x2(b0, b1);
        const float s0 = lo32(a0) + hi32(a0);
        const float s1 = lo32(b0) + hi32(b0);
        const float d0 = fmaf(s0, pen0, guard0);
        const float d1 = fmaf(s1, pen1, guard1);
        dsm[r][mpair] = make_float2(fminf(d0, d1),
                                    fminf(d0 * d0, d1 * d1));
    }
    __syncthreads();

    // ---- 8 warps reduce 16 rows (warp w -> rows w, w+8) ----
#pragma unroll
    for (int rr = 0; rr < 2; ++rr) {
        const int r = warp + rr * 8;
        float mn = INF, mn2 = INF;
#pragma unroll
        for (int i = 0; i < 4; ++i) {
            const float2 v = dsm[r][lane + i * 32];
            mn  = fminf(mn,  v.x);
            mn2 = fminf(mn2, v.y);
        }
#pragma unroll
        for (int off = 16; off; off >>= 1) {
            mn  = fminf(mn,  __shfl_xor_sync(0xffffffffu, mn,  off));
            mn2 = fminf(mn2, __shfl_xor_sync(0xffffffffu, mn2, off));
        }
        if (lane == 0) {
            const int n = n0 + r;
            const int o = (b * NN + n) * CC + c;
            out[o] = expf(-mn2);
            out[BB * NN * CC + o] = mn;
        }
    }
}

extern "C" void kernel_launch(void* const* d_in, const int* in_sizes, int n_in,
                              void* d_out, int out_size)
{
    const float* x   = (const float*)d_in[0];   // (B, C, T)
    const float* w   = (const float*)d_in[1];   // (N, C, L)
    const float* pcm = (const float*)d_in[2];   // (C, M)
    float* out = (float*)d_out;

    dim3 grid(BB * CC, NN / NBLK);              // 128 x 4 = 512 blocks
    shapelet_kernel<<<grid, 256>>>(x, w, pcm, out);
}